// round 15
// baseline (speedup 1.0000x reference)
#include <cuda_runtime.h>
#include <cuda_fp16.h>
#include <math.h>
#include <stdint.h>

// Problem constants
#define Bsz  16
#define Ssz  2048
#define Esz  512
#define Hsz  512
#define HIsz 1024
#define Lsz  3
#define Msz  (Bsz * Ssz)
#define Vsz  32000

// ---------------------------------------------------------------------------
// Scratch (__device__ globals; allocation-free)
// ---------------------------------------------------------------------------
__device__ __half g_x16f[(size_t)Msz * Hsz];
__device__ __half g_x16r[(size_t)Msz * Hsz];
__device__ __half g_hg16f[(size_t)Msz * 2 * HIsz];   // (gate, g) interleaved pairs
__device__ __half g_hg16r[(size_t)Msz * 2 * HIsz];
__device__ __half g_h16f[(size_t)Msz * HIsz];
__device__ __half g_h16r[(size_t)Msz * HIsz];
__device__ __half g_emb16[(size_t)Vsz * Esz];
#define NWELEM 9699328
__device__ __half g_w16[NWELEM];

// persistent-kernel sync state (memsetAsync to 0 before each run)
#define MAXPH 12
__device__ int      g_ctr[MAXPH];
__device__ unsigned g_bar[MAXPH];

#define OFF_ER    0
#define OFF_HGF   262144
#define OFF_OUTF  3407872
#define OFF_HGR   4980736
#define OFF_OUTR  8126464

// ---------------------------------------------------------------------------
// PTX helpers (baseline sm_103 ISA only)
// ---------------------------------------------------------------------------
__device__ __forceinline__ uint32_t s2u(const void* p) {
    uint32_t a;
    asm("{ .reg .u64 t; cvta.to.shared.u64 t, %1; cvt.u32.u64 %0, t; }" : "=r"(a) : "l"(p));
    return a;
}
__device__ __forceinline__ void cp16(uint32_t d, const void* s) {
    asm volatile("cp.async.cg.shared.global [%0], [%1], 16;" :: "r"(d), "l"(s));
}
__device__ __forceinline__ void cp_commit() { asm volatile("cp.async.commit_group;"); }
__device__ __forceinline__ void cp_wait2()  { asm volatile("cp.async.wait_group 2;"); }
__device__ __forceinline__ void cp_wait_all() { asm volatile("cp.async.wait_group 0;"); }
__device__ __forceinline__ void ldm_x4(uint32_t addr, uint32_t& r0, uint32_t& r1,
                                       uint32_t& r2, uint32_t& r3) {
    asm volatile("ldmatrix.sync.aligned.m8n8.x4.shared.b16 {%0,%1,%2,%3}, [%4];"
                 : "=r"(r0), "=r"(r1), "=r"(r2), "=r"(r3) : "r"(addr));
}
__device__ __forceinline__ void mma_fp16(float& c0, float& c1, float& c2, float& c3,
                                         uint32_t a0, uint32_t a1, uint32_t a2, uint32_t a3,
                                         uint32_t b0, uint32_t b1) {
    asm volatile("mma.sync.aligned.m16n8k16.row.col.f32.f16.f16.f32 "
                 "{%0,%1,%2,%3}, {%4,%5,%6,%7}, {%8,%9}, {%0,%1,%2,%3};"
                 : "+f"(c0), "+f"(c1), "+f"(c2), "+f"(c3)
                 : "r"(a0), "r"(a1), "r"(a2), "r"(a3), "r"(b0), "r"(b1));
}

__device__ __forceinline__ int revrow(int r, int len) {
    int s = r & (Ssz - 1);
    int t = s + Ssz - len; if (t >= Ssz) t -= Ssz;
    return (r & ~(Ssz - 1)) + (Ssz - 1 - t);
}

// (hid, gate) -> (gate, g(hid)); z and the recurrence stay fp32 in the scan
__device__ __forceinline__ float2 scanprep(float hid, float gate) {
    float g = (hid >= 0.f) ? (hid + 0.5f) : __fdividef(1.f, 1.f + __expf(-hid));
    return make_float2(gate, g);
}

// ---------------------------------------------------------------------------
// GEMM problem descriptor
// ---------------------------------------------------------------------------
struct GArgs {
    const __half* A;
    const __half* B;
    float*        C32;
    __half*       C16;
    __half*       C16b;
    const float*  bias;
    const int*    rowidx;
    const int*    lens;
    int cstride;
    int coloff;
    int c32rev;
    int sprep;
    int N;
    int K;
    int arev;
};

#define GT 256
#define ROWB 80
#define TILE_B (128 * ROWB)
#define STAGE_B (2 * TILE_B)
#define GSM (4 * STAGE_B)          // 81920 B dynamic smem

// ---------------------------------------------------------------------------
// gemm body (round-6 config, unchanged math): tile 128x128, BK=32, 8 warps
// ---------------------------------------------------------------------------
__device__ __forceinline__ void gemm_body(const GArgs& ga, int bx, int by, char* smem)
{
    const uint32_t sbase = s2u(smem);
    const int tid = threadIdx.x;
    const int wid = tid >> 5, lid = tid & 31;
    const int bm = by * 128, bn = bx * 128;
    const int wm = (wid & 1) * 64;
    const int wn = (wid >> 1) * 32;
    const int K = ga.K, N = ga.N;

    const __half* gsrc[4];
    uint32_t soff[4];
#pragma unroll
    for (int j = 0; j < 4; j++) {
        int cidx = tid + j * GT;
        int tile = cidx >> 9;
        int idx  = cidx & 511;
        int row  = idx >> 2;
        int seg  = idx & 3;
        soff[j] = (uint32_t)(tile * TILE_B + row * ROWB + seg * 16);
        if (tile == 0) {
            int r = bm + row;
            if (ga.arev) r = revrow(r, ga.lens[r >> 11]);
            long ra = ga.rowidx ? (long)ga.rowidx[r] : (long)r;
            gsrc[j] = ga.A + ra * (long)K + seg * 8;
        } else {
            gsrc[j] = ga.B + (long)(bn + row) * K + seg * 8;
        }
    }

    uint32_t aoff[4];
#pragma unroll
    for (int mt = 0; mt < 4; mt++) {
        int r = wm + mt * 16 + (lid & 15);
        int c = (lid >> 4) * 8;
        aoff[mt] = (uint32_t)(r * ROWB + c * 2);
    }
    uint32_t boff[2];
#pragma unroll
    for (int np = 0; np < 2; np++) {
        int r = wn + np * 16 + (lid & 7) + ((lid >> 4) << 3);
        int c = ((lid >> 3) & 1) * 8;
        boff[np] = (uint32_t)(TILE_B + r * ROWB + c * 2);
    }

    float acc[4][4][4];
#pragma unroll
    for (int i = 0; i < 4; i++)
#pragma unroll
        for (int j = 0; j < 4; j++)
#pragma unroll
            for (int q = 0; q < 4; q++) acc[i][j][q] = 0.f;

    const int nst = K >> 5;

    auto load_stage = [&](int s) {
        uint32_t base = sbase + (uint32_t)(s & 3) * STAGE_B;
        int ko = s << 5;
#pragma unroll
        for (int j = 0; j < 4; j++) cp16(base + soff[j], gsrc[j] + ko);
    };

    load_stage(0); cp_commit();
    load_stage(1); cp_commit();
    load_stage(2); cp_commit();

    for (int s = 0; s < nst; s++) {
        cp_wait2();
        __syncthreads();
        if (s + 3 < nst) load_stage(s + 3);
        cp_commit();

        uint32_t base = sbase + (uint32_t)(s & 3) * STAGE_B;
#pragma unroll
        for (int k16 = 0; k16 < 2; k16++) {
            uint32_t koff = (uint32_t)(k16 * 32);
            uint32_t af[4][4];
#pragma unroll
            for (int mt = 0; mt < 4; mt++)
                ldm_x4(base + aoff[mt] + koff, af[mt][0], af[mt][1], af[mt][2], af[mt][3]);
            uint32_t bf[4][2];
#pragma unroll
            for (int np = 0; np < 2; np++) {
                uint32_t r0, r1, r2, r3;
                ldm_x4(base + boff[np] + koff, r0, r1, r2, r3);
                bf[np * 2][0] = r0;     bf[np * 2][1] = r1;
                bf[np * 2 + 1][0] = r2; bf[np * 2 + 1][1] = r3;
            }
#pragma unroll
            for (int mt = 0; mt < 4; mt++)
#pragma unroll
                for (int nt = 0; nt < 4; nt++)
                    mma_fp16(acc[mt][nt][0], acc[mt][nt][1], acc[mt][nt][2], acc[mt][nt][3],
                             af[mt][0], af[mt][1], af[mt][2], af[mt][3],
                             bf[nt][0], bf[nt][1]);
        }
    }
    cp_wait_all();           // drain before this CTA reuses smem for the next unit
    __syncthreads();

    int len = ga.lens ? ga.lens[bm >> 11] : 0;
#pragma unroll
    for (int mt = 0; mt < 4; mt++) {
        int rA = bm + wm + mt * 16 + (lid >> 2);
        int rB = rA + 8;
        int rAm = ga.lens ? revrow(rA, len) : 0;
        int rBm = ga.lens ? revrow(rB, len) : 0;
#pragma unroll
        for (int nt = 0; nt < 4; nt++) {
            int col = bn + wn + nt * 8 + (lid & 3) * 2;
            float v0 = acc[mt][nt][0], v1 = acc[mt][nt][1];
            float v2 = acc[mt][nt][2], v3 = acc[mt][nt][3];
            if (ga.bias) {
                float2 bb = *(const float2*)(ga.bias + col);
                v0 += bb.x; v1 += bb.y; v2 += bb.x; v3 += bb.y;
            }
            if (ga.sprep) {
                float2 cv0 = scanprep(v0, v1);
                float2 cv1 = scanprep(v2, v3);
                v0 = cv0.x; v1 = cv0.y; v2 = cv1.x; v3 = cv1.y;
            }
            if (ga.C32) {
                int wA = ga.c32rev ? rAm : rA;
                int wB = ga.c32rev ? rBm : rB;
                *(float2*)(ga.C32 + (size_t)wA * ga.cstride + ga.coloff + col) = make_float2(v0, v1);
                *(float2*)(ga.C32 + (size_t)wB * ga.cstride + ga.coloff + col) = make_float2(v2, v3);
            }
            if (ga.C16) {
                *(__half2*)(ga.C16 + (size_t)rA * ga.cstride + col) = __floats2half2_rn(v0, v1);
                *(__half2*)(ga.C16 + (size_t)rB * ga.cstride + col) = __floats2half2_rn(v2, v3);
            }
            if (ga.C16b) {
                *(__half2*)(ga.C16b + (size_t)rAm * ga.cstride + col) = __floats2half2_rn(v0, v1);
                *(__half2*)(ga.C16b + (size_t)rBm * ga.cstride + col) = __floats2half2_rn(v2, v3);
            }
        }
    }
}

// ---------------------------------------------------------------------------
// scan body (round-11 config): 64 units/direction, 256 channels/unit.
// ---------------------------------------------------------------------------
#define SCT 16
#define SSTAGE_B 16384

__device__ __forceinline__ void scan_body(const __half* __restrict__ hg,
                                          __half* __restrict__ h,
                                          int sid, char* smem)
{
    const uint32_t sb = s2u(smem);
    const int tid = threadIdx.x;
    const int b = sid >> 2;
    const int cblk = (sid & 3) << 8;

    const __half* hgp = hg + (size_t)b * Ssz * 2 * HIsz + 2 * cblk;
    __half* hp = h + (size_t)b * Ssz * HIsz + cblk + tid;

    const __half* gsl[4];
    uint32_t ssl[4];
#pragma unroll
    for (int j = 0; j < 4; j++) {
        int lin = tid + 256 * j;
        int u   = lin >> 6;
        int seg = lin & 63;
        gsl[j] = hgp + (size_t)u * 2 * HIsz + seg * 8;
        ssl[j] = (uint32_t)(u * 1024 + seg * 16);
    }

    auto load_stage = [&](int st) {
        uint32_t base = sb + (uint32_t)(st & 3) * SSTAGE_B;
        size_t go = (size_t)st * SCT * 2 * HIsz;
#pragma unroll
        for (int j = 0; j < 4; j++) cp16(base + ssl[j], gsl[j] + go);
        cp_commit();
    };

    load_stage(0);
    load_stage(1);
    load_stage(2);

    const int NST = Ssz / SCT;
    float hv = 0.f;
    for (int st = 0; st < NST; st++) {
        cp_wait2();
        __syncthreads();
        if (st + 3 < NST) load_stage(st + 3);

        const __half2* base = (const __half2*)(smem + (size_t)(st & 3) * SSTAGE_B);
#pragma unroll
        for (int u = 0; u < SCT; u++) {
            float2 gg = __half22float2(base[u * 256 + tid]);
            float z = __fdividef(1.f, 1.f + __expf(-gg.x));
            hv += z * (gg.y - hv);
            hp[(size_t)(st * SCT + u) * HIsz] = __float2half(hv);
        }
    }
    cp_wait_all();
    __syncthreads();
}

// ---------------------------------------------------------------------------
// persistent kernel: phases with software grid barriers.
// All NCTA CTAs are co-resident (regs<=128 via launch_bounds, smem 80KB -> 2/SM).
// ---------------------------------------------------------------------------
#define NCTA 296

struct Phase {
    GArgs a0, a1;
    const __half* sHG;
    __half* sH;
    int nscan, nb0, nx0, nb1, nx1;
};
struct PhaseSet {
    Phase ph[MAXPH];
    int np;
};

__global__ __launch_bounds__(GT, 2)
void persist_kernel(PhaseSet ps)
{
    extern __shared__ char smem[];
    __shared__ int s_u;

    for (int p = 0; p < ps.np; p++) {
        const Phase& ph = ps.ph[p];
        const int ntot = ph.nscan + ph.nb0 + ph.nb1;

        for (;;) {
            __syncthreads();
            if (threadIdx.x == 0) s_u = atomicAdd(&g_ctr[p], 1);
            __syncthreads();
            int u = s_u;
            if (u >= ntot) break;
            if (u < ph.nscan) {
                scan_body(ph.sHG, ph.sH, u, smem);
            } else {
                u -= ph.nscan;
                if (u < ph.nb0) gemm_body(ph.a0, u % ph.nx0, u / ph.nx0, smem);
                else { u -= ph.nb0; gemm_body(ph.a1, u % ph.nx1, u / ph.nx1, smem); }
            }
        }

        if (p + 1 < ps.np) {
            __syncthreads();
            if (threadIdx.x == 0) {
                __threadfence();
                atomicAdd(&g_bar[p], 1u);
                while (*((volatile unsigned*)&g_bar[p]) < (unsigned)NCTA)
                    __nanosleep(128);
            }
            __syncthreads();
            __threadfence();
        }
    }
}

// ---------------------------------------------------------------------------
// prologue kernels (unchanged)
// ---------------------------------------------------------------------------
__global__ void wconv_batch_kernel(const float* __restrict__ Wf, const float* __restrict__ Wr,
                                   __half* __restrict__ Tf, __half* __restrict__ Tr,
                                   int K, int N, int perm)
{
    __shared__ float t[32][33];
    int z = blockIdx.z;
    int l = (z >= 3) ? z - 3 : z;
    const float* W = ((z >= 3) ? Wr : Wf) + (size_t)l * K * N;
    __half*      T = ((z >= 3) ? Tr : Tf) + (size_t)l * K * N;
    int n0 = blockIdx.x * 32, k0 = blockIdx.y * 32;
    int tx = threadIdx.x, ty = threadIdx.y;
    for (int r = ty; r < 32; r += 8)
        t[r][tx] = W[(size_t)(k0 + r) * N + n0 + tx];
    __syncthreads();
    for (int r = ty; r < 32; r += 8) {
        int nn = n0 + r;
        int prow = perm ? ((nn < HIsz) ? 2 * nn : 2 * (nn - HIsz) + 1) : nn;
        T[(size_t)prow * K + k0 + tx] = __float2half(t[tx][r]);
    }
}

__global__ void wconv_kernel(const float* __restrict__ W, __half* __restrict__ T,
                             int K, int N)
{
    __shared__ float t[32][33];
    int n0 = blockIdx.x * 32, k0 = blockIdx.y * 32;
    int tx = threadIdx.x, ty = threadIdx.y;
    for (int r = ty; r < 32; r += 8)
        t[r][tx] = W[(size_t)(k0 + r) * N + n0 + tx];
    __syncthreads();
    for (int r = ty; r < 32; r += 8)
        T[(size_t)(n0 + r) * K + k0 + tx] = __float2half(t[tx][r]);
}

__global__ void conv_kernel(const float* __restrict__ x, __half* __restrict__ y, size_t n)
{
    size_t i = ((size_t)blockIdx.x * blockDim.x + threadIdx.x) * 8;
    if (i >= n) return;
    float4 a = *(const float4*)(x + i);
    float4 b = *(const float4*)(x + i + 4);
    struct alignas(16) H8 { __half2 d[4]; } o;
    o.d[0] = __floats2half2_rn(a.x, a.y);
    o.d[1] = __floats2half2_rn(a.z, a.w);
    o.d[2] = __floats2half2_rn(b.x, b.y);
    o.d[3] = __floats2half2_rn(b.z, b.w);
    *(H8*)(y + i) = o;
}

__global__ void seq_kernel(const float* __restrict__ out, const int* __restrict__ lens,
                           float* __restrict__ seq)
{
    int b = blockIdx.x;
    int len = lens[b];
    const float* row = out + ((size_t)b * Ssz + (len - 1)) * 2 * Hsz;
    for (int j = threadIdx.x; j < 2 * Hsz; j += blockDim.x)
        seq[(size_t)b * 2 * Hsz + j] = row[j];
}

// ---------------------------------------------------------------------------
extern "C" void kernel_launch(void* const* d_in, const int* in_sizes, int n_in,
                              void* d_out, int out_size)
{
    const int*   x_source  = (const int*)  d_in[0];
    const int*   x_lengths = (const int*)  d_in[1];
    const float* emb       = (const float*)d_in[2];
    const float* W_er      = (const float*)d_in[3];
    const float* b_er      = (const float*)d_in[4];
    const float* Whg_f     = (const float*)d_in[5];
    const float* Wout_f    = (const float*)d_in[6];
    const float* Whg_r     = (const float*)d_in[7];
    const float* Wout_r    = (const float*)d_in[8];
    float* out = (float*)d_out;

    __half *x16f, *x16r, *hg16f, *hg16r, *h16f, *h16r, *emb16, *w16;
    void *ctrp, *barp;
    cudaGetSymbolAddress((void**)&x16f,  g_x16f);
    cudaGetSymbolAddress((void**)&x16r,  g_x16r);
    cudaGetSymbolAddress((void**)&hg16f, g_hg16f);
    cudaGetSymbolAddress((void**)&hg16r, g_hg16r);
    cudaGetSymbolAddress((void**)&h16f,  g_h16f);
    cudaGetSymbolAddress((void**)&h16r,  g_h16r);
    cudaGetSymbolAddress((void**)&emb16, g_emb16);
    cudaGetSymbolAddress((void**)&w16,   g_w16);
    cudaGetSymbolAddress(&ctrp, g_ctr);
    cudaGetSymbolAddress(&barp, g_bar);

    cudaFuncSetAttribute(persist_kernel, cudaFuncAttributeMaxDynamicSharedMemorySize, GSM);

    const int HG_NB = 16 * 256, HG_NX = 16;
    const int OUT_NB = 4 * 256, OUT_NX = 4;
    const int NSCAN = 64;

    // prologue converts
    wconv_batch_kernel<<<dim3(2 * HIsz / 32, Hsz / 32, 6), dim3(32, 8)>>>(
        Whg_f, Whg_r, w16 + OFF_HGF, w16 + OFF_HGR, Hsz, 2 * HIsz, 1);
    wconv_batch_kernel<<<dim3(Hsz / 32, HIsz / 32, 6), dim3(32, 8)>>>(
        Wout_f, Wout_r, w16 + OFF_OUTF, w16 + OFF_OUTR, HIsz, Hsz, 0);
    wconv_kernel<<<dim3(Hsz / 32, Esz / 32), dim3(32, 8)>>>(W_er, w16 + OFF_ER, Esz, Hsz);
    conv_kernel<<<(unsigned)(((size_t)Vsz * Esz) / 2048), 256>>>(emb, emb16, (size_t)Vsz * Esz);

    // reset persistent-kernel sync state (graph-legal async memset)
    cudaMemsetAsync(ctrp, 0, sizeof(int) * MAXPH);
    cudaMemsetAsync(barp, 0, sizeof(unsigned) * MAXPH);

    auto HG = [&](int l, int dir) {
        int ar = (dir && l == 0) ? 1 : 0;
        GArgs a = { (dir && !ar) ? x16r : x16f,
                    w16 + (dir ? OFF_HGR : OFF_HGF) + (size_t)l * 1048576,
                    nullptr, dir ? hg16r : hg16f, nullptr, nullptr, nullptr,
                    ar ? x_lengths : nullptr,
                    2 * HIsz, 0, 0, 1, 2 * HIsz, Hsz, ar };
        return a;
    };
    auto OUTm = [&](int l, int dir) {
        GArgs a = { dir ? h16r : h16f,
                    w16 + (dir ? OFF_OUTR : OFF_OUTF) + (size_t)l * 524288,
                    nullptr, dir ? x16r : x16f, nullptr, nullptr, nullptr, nullptr,
                    Hsz, 0, 0, 0, Hsz, HIsz, 0 };
        return a;
    };
    auto OUTf = [&](int dir) {
        GArgs a = { dir ? h16r : h16f,
                    w16 + (dir ? OFF_OUTR : OFF_OUTF) + (size_t)2 * 524288,
                    out, nullptr, nullptr, nullptr, nullptr, x_lengths,
                    2 * Hsz, dir ? Hsz : 0, dir ? 1 : 0, 0, Hsz, HIsz, 0 };
        return a;
    };
    GArgs ZERO = {};

    PhaseSet ps;
    int p = 0;
    auto addPhase = [&](GArgs a0, int nb0, int nx0, GArgs a1, int nb1, int nx1,
                        int nscan, const __half* sHG, __half* sH) {
        Phase& f = ps.ph[p++];
        f.a0 = a0; f.a1 = a1; f.nb0 = nb0; f.nx0 = nx0; f.nb1 = nb1; f.nx1 = nx1;
        f.nscan = nscan; f.sHG = sHG; f.sH = sH;
    };

    // P0: embed GEMM -> x16f (x16r never materialized; hgR0 gathers inline)
    {
        GArgs a = { emb16, w16 + OFF_ER, nullptr, x16f, nullptr, b_er, x_source,
                    nullptr, Hsz, 0, 0, 0, Hsz, Esz, 0 };
        addPhase(a, OUT_NB, OUT_NX, ZERO, 0, 1, 0, nullptr, nullptr);
    }
    // P1: hgF0
    addPhase(HG(0, 0), HG_NB, HG_NX, ZERO, 0, 1, 0, nullptr, nullptr);
    for (int l = 0; l < Lsz; l++) {
        // scanF(l) ∥ hgR(l)
        addPhase(HG(l, 1), HG_NB, HG_NX, ZERO, 0, 1, NSCAN, hg16f, h16f);
        // scanR(l) ∥ outF(l)
        addPhase((l == Lsz - 1) ? OUTf(0) : OUTm(l, 0), OUT_NB, OUT_NX, ZERO, 0, 1,
                 NSCAN, hg16r, h16r);
        if (l + 1 < Lsz) {
            // hgF(l+1) ∥ outR(l)
            addPhase(HG(l + 1, 0), HG_NB, HG_NX, OUTm(l, 1), OUT_NB, OUT_NX,
                     0, nullptr, nullptr);
        } else {
            // outR(last) -> fp32 out
            addPhase(OUTf(1), OUT_NB, OUT_NX, ZERO, 0, 1, 0, nullptr, nullptr);
        }
    }
    ps.np = p;   // 11 phases

    persist_kernel<<<NCTA, GT, GSM>>>(ps);

    long long need = (long long)Msz * 2 * Hsz + (long long)Bsz * 2 * Hsz;
    if ((long long)out_size >= need)
        seq_kernel<<<Bsz, 256>>>(out, x_lengths, out + (size_t)Msz * 2 * Hsz);
}

// round 16
// speedup vs baseline: 1.0817x; 1.0817x over previous
#include <cuda_runtime.h>
#include <cuda_fp16.h>
#include <math.h>
#include <stdint.h>

// Problem constants
#define Bsz  16
#define Ssz  2048
#define Esz  512
#define Hsz  512
#define HIsz 1024
#define Lsz  3
#define Msz  (Bsz * Ssz)
#define Vsz  32000

// ---------------------------------------------------------------------------
// Scratch (__device__ globals; allocation-free)
// ---------------------------------------------------------------------------
__device__ __half g_x16f[(size_t)Msz * Hsz];
__device__ __half g_x16r[(size_t)Msz * Hsz];
__device__ __half g_hg16f[(size_t)Msz * 2 * HIsz];   // (gate, g) interleaved pairs
__device__ __half g_hg16r[(size_t)Msz * 2 * HIsz];
__device__ __half g_h16f[(size_t)Msz * HIsz];
__device__ __half g_h16r[(size_t)Msz * HIsz];
__device__ __half g_emb16[(size_t)Vsz * Esz];
#define NWELEM 9699328
__device__ __half g_w16[NWELEM];

#define OFF_ER    0
#define OFF_HGF   262144
#define OFF_OUTF  3407872
#define OFF_HGR   4980736
#define OFF_OUTR  8126464

// ---------------------------------------------------------------------------
// PTX helpers (baseline sm_103 ISA only)
// ---------------------------------------------------------------------------
__device__ __forceinline__ uint32_t s2u(const void* p) {
    uint32_t a;
    asm("{ .reg .u64 t; cvta.to.shared.u64 t, %1; cvt.u32.u64 %0, t; }" : "=r"(a) : "l"(p));
    return a;
}
__device__ __forceinline__ void cp16(uint32_t d, const void* s) {
    asm volatile("cp.async.cg.shared.global [%0], [%1], 16;" :: "r"(d), "l"(s));
}
__device__ __forceinline__ void cp_commit() { asm volatile("cp.async.commit_group;"); }
__device__ __forceinline__ void cp_wait2()  { asm volatile("cp.async.wait_group 2;"); }
__device__ __forceinline__ void ldm_x4(uint32_t addr, uint32_t& r0, uint32_t& r1,
                                       uint32_t& r2, uint32_t& r3) {
    asm volatile("ldmatrix.sync.aligned.m8n8.x4.shared.b16 {%0,%1,%2,%3}, [%4];"
                 : "=r"(r0), "=r"(r1), "=r"(r2), "=r"(r3) : "r"(addr));
}
__device__ __forceinline__ void mma_fp16(float& c0, float& c1, float& c2, float& c3,
                                         uint32_t a0, uint32_t a1, uint32_t a2, uint32_t a3,
                                         uint32_t b0, uint32_t b1) {
    asm volatile("mma.sync.aligned.m16n8k16.row.col.f32.f16.f16.f32 "
                 "{%0,%1,%2,%3}, {%4,%5,%6,%7}, {%8,%9}, {%0,%1,%2,%3};"
                 : "+f"(c0), "+f"(c1), "+f"(c2), "+f"(c3)
                 : "r"(a0), "r"(a1), "r"(a2), "r"(a3), "r"(b0), "r"(b1));
}

__device__ __forceinline__ int revrow(int r, int len) {
    int s = r & (Ssz - 1);
    int t = s + Ssz - len; if (t >= Ssz) t -= Ssz;
    return (r & ~(Ssz - 1)) + (Ssz - 1 - t);
}

// (hid, gate) -> (gate, g(hid)); z and the recurrence stay fp32 in the scan
__device__ __forceinline__ float2 scanprep(float hid, float gate) {
    float g = (hid >= 0.f) ? (hid + 0.5f) : __fdividef(1.f, 1.f + __expf(-hid));
    return make_float2(gate, g);
}

// ---------------------------------------------------------------------------
// GEMM problem descriptor
// ---------------------------------------------------------------------------
struct GArgs {
    const __half* A;
    const __half* B;
    float*        C32;
    __half*       C16;
    __half*       C16b;
    const float*  bias;
    const int*    rowidx;
    const int*    lens;
    int cstride;
    int coloff;
    int c32rev;
    int sprep;
    int N;
    int K;
    int arev;      // gather A rows via revrow(lens) instead of identity
};

#define GT 256
#define ROWB 80
#define TILE_B (128 * ROWB)
#define STAGE_B (2 * TILE_B)
#define GSM (4 * STAGE_B)          // 81920 B dynamic smem

// ---------------------------------------------------------------------------
// gemm body (round-6 config, unchanged math): tile 128x128, BK=32, 8 warps
// ---------------------------------------------------------------------------
__device__ __forceinline__ void gemm_body(const GArgs& ga, int bx, int by, char* smem)
{
    const uint32_t sbase = s2u(smem);
    const int tid = threadIdx.x;
    const int wid = tid >> 5, lid = tid & 31;
    const int bm = by * 128, bn = bx * 128;
    const int wm = (wid & 1) * 64;
    const int wn = (wid >> 1) * 32;
    const int K = ga.K, N = ga.N;

    const __half* gsrc[4];
    uint32_t soff[4];
#pragma unroll
    for (int j = 0; j < 4; j++) {
        int cidx = tid + j * GT;
        int tile = cidx >> 9;
        int idx  = cidx & 511;
        int row  = idx >> 2;
        int seg  = idx & 3;
        soff[j] = (uint32_t)(tile * TILE_B + row * ROWB + seg * 16);
        if (tile == 0) {
            int r = bm + row;
            if (ga.arev) r = revrow(r, ga.lens[r >> 11]);
            long ra = ga.rowidx ? (long)ga.rowidx[r] : (long)r;
            gsrc[j] = ga.A + ra * (long)K + seg * 8;
        } else {
            gsrc[j] = ga.B + (long)(bn + row) * K + seg * 8;
        }
    }

    uint32_t aoff[4];
#pragma unroll
    for (int mt = 0; mt < 4; mt++) {
        int r = wm + mt * 16 + (lid & 15);
        int c = (lid >> 4) * 8;
        aoff[mt] = (uint32_t)(r * ROWB + c * 2);
    }
    uint32_t boff[2];
#pragma unroll
    for (int np = 0; np < 2; np++) {
        int r = wn + np * 16 + (lid & 7) + ((lid >> 4) << 3);
        int c = ((lid >> 3) & 1) * 8;
        boff[np] = (uint32_t)(TILE_B + r * ROWB + c * 2);
    }

    float acc[4][4][4];
#pragma unroll
    for (int i = 0; i < 4; i++)
#pragma unroll
        for (int j = 0; j < 4; j++)
#pragma unroll
            for (int q = 0; q < 4; q++) acc[i][j][q] = 0.f;

    const int nst = K >> 5;

    auto load_stage = [&](int s) {
        uint32_t base = sbase + (uint32_t)(s & 3) * STAGE_B;
        int ko = s << 5;
#pragma unroll
        for (int j = 0; j < 4; j++) cp16(base + soff[j], gsrc[j] + ko);
    };

    load_stage(0); cp_commit();
    load_stage(1); cp_commit();
    load_stage(2); cp_commit();

    for (int s = 0; s < nst; s++) {
        cp_wait2();
        __syncthreads();
        if (s + 3 < nst) load_stage(s + 3);
        cp_commit();

        uint32_t base = sbase + (uint32_t)(s & 3) * STAGE_B;
#pragma unroll
        for (int k16 = 0; k16 < 2; k16++) {
            uint32_t koff = (uint32_t)(k16 * 32);
            uint32_t af[4][4];
#pragma unroll
            for (int mt = 0; mt < 4; mt++)
                ldm_x4(base + aoff[mt] + koff, af[mt][0], af[mt][1], af[mt][2], af[mt][3]);
            uint32_t bf[4][2];
#pragma unroll
            for (int np = 0; np < 2; np++) {
                uint32_t r0, r1, r2, r3;
                ldm_x4(base + boff[np] + koff, r0, r1, r2, r3);
                bf[np * 2][0] = r0;     bf[np * 2][1] = r1;
                bf[np * 2 + 1][0] = r2; bf[np * 2 + 1][1] = r3;
            }
#pragma unroll
            for (int mt = 0; mt < 4; mt++)
#pragma unroll
                for (int nt = 0; nt < 4; nt++)
                    mma_fp16(acc[mt][nt][0], acc[mt][nt][1], acc[mt][nt][2], acc[mt][nt][3],
                             af[mt][0], af[mt][1], af[mt][2], af[mt][3],
                             bf[nt][0], bf[nt][1]);
        }
    }

    int len = ga.lens ? ga.lens[bm >> 11] : 0;
#pragma unroll
    for (int mt = 0; mt < 4; mt++) {
        int rA = bm + wm + mt * 16 + (lid >> 2);
        int rB = rA + 8;
        int rAm = ga.lens ? revrow(rA, len) : 0;
        int rBm = ga.lens ? revrow(rB, len) : 0;
#pragma unroll
        for (int nt = 0; nt < 4; nt++) {
            int col = bn + wn + nt * 8 + (lid & 3) * 2;
            float v0 = acc[mt][nt][0], v1 = acc[mt][nt][1];
            float v2 = acc[mt][nt][2], v3 = acc[mt][nt][3];
            if (ga.bias) {
                float2 bb = *(const float2*)(ga.bias + col);
                v0 += bb.x; v1 += bb.y; v2 += bb.x; v3 += bb.y;
            }
            if (ga.sprep) {
                float2 cv0 = scanprep(v0, v1);
                float2 cv1 = scanprep(v2, v3);
                v0 = cv0.x; v1 = cv0.y; v2 = cv1.x; v3 = cv1.y;
            }
            if (ga.C32) {
                int wA = ga.c32rev ? rAm : rA;
                int wB = ga.c32rev ? rBm : rB;
                *(float2*)(ga.C32 + (size_t)wA * ga.cstride + ga.coloff + col) = make_float2(v0, v1);
                *(float2*)(ga.C32 + (size_t)wB * ga.cstride + ga.coloff + col) = make_float2(v2, v3);
            }
            if (ga.C16) {
                *(__half2*)(ga.C16 + (size_t)rA * ga.cstride + col) = __floats2half2_rn(v0, v1);
                *(__half2*)(ga.C16 + (size_t)rB * ga.cstride + col) = __floats2half2_rn(v2, v3);
            }
            if (ga.C16b) {
                *(__half2*)(ga.C16b + (size_t)rAm * ga.cstride + col) = __floats2half2_rn(v0, v1);
                *(__half2*)(ga.C16b + (size_t)rBm * ga.cstride + col) = __floats2half2_rn(v2, v3);
            }
        }
    }
}

// ---------------------------------------------------------------------------
// scan body (round-11 config): 64 blocks/direction, 256 channels/block.
// (gate,g) fp16 pairs in; h fp16 out; z + recurrence fp32.
// Stage = 16 steps x 256 ch x 4B = 16KB; 4 stages in dyn smem.
// ---------------------------------------------------------------------------
#define SCT 16
#define SSTAGE_B 16384

__device__ __forceinline__ void scan_body(const __half* __restrict__ hg,
                                          __half* __restrict__ h,
                                          int sid, char* smem)
{
    const uint32_t sb = s2u(smem);
    const int tid = threadIdx.x;
    const int b = sid >> 2;
    const int cblk = (sid & 3) << 8;              // 256-channel block

    const __half* hgp = hg + (size_t)b * Ssz * 2 * HIsz + 2 * cblk;
    __half* hp = h + (size_t)b * Ssz * HIsz + cblk + tid;

    const __half* gsl[4];
    uint32_t ssl[4];
#pragma unroll
    for (int j = 0; j < 4; j++) {
        int lin = tid + 256 * j;                  // 0..1023
        int u   = lin >> 6;                       // step 0..15
        int seg = lin & 63;                       // 16B segment of 1KB row
        gsl[j] = hgp + (size_t)u * 2 * HIsz + seg * 8;
        ssl[j] = (uint32_t)(u * 1024 + seg * 16);
    }

    auto load_stage = [&](int st) {
        uint32_t base = sb + (uint32_t)(st & 3) * SSTAGE_B;
        size_t go = (size_t)st * SCT * 2 * HIsz;
#pragma unroll
        for (int j = 0; j < 4; j++) cp16(base + ssl[j], gsl[j] + go);
        cp_commit();
    };

    load_stage(0);
    load_stage(1);
    load_stage(2);

    const int NST = Ssz / SCT;
    float hv = 0.f;
    for (int st = 0; st < NST; st++) {
        cp_wait2();
        __syncthreads();
        if (st + 3 < NST) load_stage(st + 3);

        const __half2* base = (const __half2*)(smem + (size_t)(st & 3) * SSTAGE_B);
#pragma unroll
        for (int u = 0; u < SCT; u++) {
            float2 gg = __half22float2(base[u * 256 + tid]);     // (gate, g)
            float z = __fdividef(1.f, 1.f + __expf(-gg.x));      // fp32 sigmoid
            hv += z * (gg.y - hv);
            hp[(size_t)(st * SCT + u) * HIsz] = __float2half(hv);
        }
    }
}

// ---------------------------------------------------------------------------
// mega kernel: [scan blocks][gemm problem 0 blocks][gemm problem 1 blocks]
// ---------------------------------------------------------------------------
__global__ __launch_bounds__(GT, 2)
void mega_kernel(GArgs ga0, GArgs ga1, int nscan, int nb0, int nx0, int nx1,
                 const __half* sHG, __half* sH)
{
    extern __shared__ char smem[];
    int bid = blockIdx.x;
    if (bid < nscan) { scan_body(sHG, sH, bid, smem); return; }
    bid -= nscan;
    if (bid < nb0) {
        gemm_body(ga0, bid % nx0, bid / nx0, smem);
    } else {
        bid -= nb0;
        gemm_body(ga1, bid % nx1, bid / nx1, smem);
    }
}

// ---------------------------------------------------------------------------
// merged weight transpose+convert: z<6 -> HG [512 -> 2048, perm],
// z>=6 -> OUT [1024 -> 512, no perm]. Grid sized for HG (64 x 16); OUT
// tiles use a subset (16 x 32 of the 64 x 16 space remapped).
// ---------------------------------------------------------------------------
__global__ void wconv_all_kernel(const float* __restrict__ Whgf, const float* __restrict__ Whgr,
                                 const float* __restrict__ Woutf, const float* __restrict__ Woutr,
                                 __half* __restrict__ w16)
{
    __shared__ float t[32][33];
    int z = blockIdx.z;
    const float* W;
    __half* T;
    int K, N, perm, n0, k0;
    if (z < 6) {                      // HG: K=512, N=2048; grid.x=64 (n), grid.y=16 (k)
        int l = (z >= 3) ? z - 3 : z;
        W = ((z >= 3) ? Whgr : Whgf) + (size_t)l * Hsz * 2 * HIsz;
        T = w16 + ((z >= 3) ? OFF_HGR : OFF_HGF) + (size_t)l * 1048576;
        K = Hsz; N = 2 * HIsz; perm = 1;
        n0 = blockIdx.x * 32; k0 = blockIdx.y * 32;
    } else {                          // OUT: K=1024, N=512; remap 1024 blocks -> 16 x 32
        int z2 = z - 6;
        int l = (z2 >= 3) ? z2 - 3 : z2;
        W = ((z2 >= 3) ? Woutr : Woutf) + (size_t)l * HIsz * Hsz;
        T = w16 + ((z2 >= 3) ? OFF_OUTR : OFF_OUTF) + (size_t)l * 524288;
        K = HIsz; N = Hsz; perm = 0;
        int lin = blockIdx.y * 64 + blockIdx.x;    // 0..1023
        if (lin >= 512) return;
        n0 = (lin & 15) * 32; k0 = (lin >> 4) * 32;
    }
    int tx = threadIdx.x, ty = threadIdx.y;
    for (int r = ty; r < 32; r += 8)
        t[r][tx] = W[(size_t)(k0 + r) * N + n0 + tx];
    __syncthreads();
    for (int r = ty; r < 32; r += 8) {
        int nn = n0 + r;
        int prow = perm ? ((nn < HIsz) ? 2 * nn : 2 * (nn - HIsz) + 1) : nn;
        T[(size_t)prow * K + k0 + tx] = __float2half(t[tx][r]);
    }
}

__global__ void wconv_kernel(const float* __restrict__ W, __half* __restrict__ T,
                             int K, int N)
{
    __shared__ float t[32][33];
    int n0 = blockIdx.x * 32, k0 = blockIdx.y * 32;
    int tx = threadIdx.x, ty = threadIdx.y;
    for (int r = ty; r < 32; r += 8)
        t[r][tx] = W[(size_t)(k0 + r) * N + n0 + tx];
    __syncthreads();
    for (int r = ty; r < 32; r += 8)
        T[(size_t)(n0 + r) * K + k0 + tx] = __float2half(t[tx][r]);
}

__global__ void conv_kernel(const float* __restrict__ x, __half* __restrict__ y, size_t n)
{
    size_t i = ((size_t)blockIdx.x * blockDim.x + threadIdx.x) * 8;
    if (i >= n) return;
    float4 a = *(const float4*)(x + i);
    float4 b = *(const float4*)(x + i + 4);
    struct alignas(16) H8 { __half2 d[4]; } o;
    o.d[0] = __floats2half2_rn(a.x, a.y);
    o.d[1] = __floats2half2_rn(a.z, a.w);
    o.d[2] = __floats2half2_rn(b.x, b.y);
    o.d[3] = __floats2half2_rn(b.z, b.w);
    *(H8*)(y + i) = o;
}

__global__ void seq_kernel(const float* __restrict__ out, const int* __restrict__ lens,
                           float* __restrict__ seq)
{
    int b = blockIdx.x;
    int len = lens[b];
    const float* row = out + ((size_t)b * Ssz + (len - 1)) * 2 * Hsz;
    for (int j = threadIdx.x; j < 2 * Hsz; j += blockDim.x)
        seq[(size_t)b * 2 * Hsz + j] = row[j];
}

// ---------------------------------------------------------------------------
extern "C" void kernel_launch(void* const* d_in, const int* in_sizes, int n_in,
                              void* d_out, int out_size)
{
    const int*   x_source  = (const int*)  d_in[0];
    const int*   x_lengths = (const int*)  d_in[1];
    const float* emb       = (const float*)d_in[2];
    const float* W_er      = (const float*)d_in[3];
    const float* b_er      = (const float*)d_in[4];
    const float* Whg_f     = (const float*)d_in[5];
    const float* Wout_f    = (const float*)d_in[6];
    const float* Whg_r     = (const float*)d_in[7];
    const float* Wout_r    = (const float*)d_in[8];
    float* out = (float*)d_out;

    __half *x16f, *x16r, *hg16f, *hg16r, *h16f, *h16r, *emb16, *w16;
    cudaGetSymbolAddress((void**)&x16f,  g_x16f);
    cudaGetSymbolAddress((void**)&x16r,  g_x16r);
    cudaGetSymbolAddress((void**)&hg16f, g_hg16f);
    cudaGetSymbolAddress((void**)&hg16r, g_hg16r);
    cudaGetSymbolAddress((void**)&h16f,  g_h16f);
    cudaGetSymbolAddress((void**)&h16r,  g_h16r);
    cudaGetSymbolAddress((void**)&emb16, g_emb16);
    cudaGetSymbolAddress((void**)&w16,   g_w16);

    cudaFuncSetAttribute(mega_kernel, cudaFuncAttributeMaxDynamicSharedMemorySize, GSM);

    const int HG_NB = 16 * 256, HG_NX = 16;      // N=2048 gemm
    const int OUT_NB = 4 * 256, OUT_NX = 4;      // N=512 gemm
    const int NSCAN = 64;

    // prologue: merged layer-weight convert + embed deps
    wconv_all_kernel<<<dim3(64, 16, 12), dim3(32, 8)>>>(Whg_f, Whg_r, Wout_f, Wout_r, w16);
    wconv_kernel<<<dim3(Hsz / 32, Esz / 32), dim3(32, 8)>>>(W_er, w16 + OFF_ER, Esz, Hsz);
    conv_kernel<<<(unsigned)(((size_t)Vsz * Esz) / 2048), 256>>>(emb, emb16, (size_t)Vsz * Esz);

    auto HG = [&](int l, int dir) {
        // hgR(0) reads x16f via inline revrow gather (arev); others plain
        int ar = (dir && l == 0) ? 1 : 0;
        GArgs a = { (dir && !ar) ? x16r : x16f,
                    w16 + (dir ? OFF_HGR : OFF_HGF) + (size_t)l * 1048576,
                    nullptr, dir ? hg16r : hg16f, nullptr, nullptr, nullptr,
                    ar ? x_lengths : nullptr,
                    2 * HIsz, 0, 0, 1, 2 * HIsz, Hsz, ar };
        return a;
    };
    auto OUTm = [&](int l, int dir) {
        GArgs a = { dir ? h16r : h16f,
                    w16 + (dir ? OFF_OUTR : OFF_OUTF) + (size_t)l * 524288,
                    nullptr, dir ? x16r : x16f, nullptr, nullptr, nullptr, nullptr,
                    Hsz, 0, 0, 0, Hsz, HIsz, 0 };
        return a;
    };
    auto OUTf = [&](int dir) {
        GArgs a = { dir ? h16r : h16f,
                    w16 + (dir ? OFF_OUTR : OFF_OUTF) + (size_t)2 * 524288,
                    out, nullptr, nullptr, nullptr, nullptr, x_lengths,
                    2 * Hsz, dir ? Hsz : 0, dir ? 1 : 0, 0, Hsz, HIsz, 0 };
        return a;
    };

    // embed GEMM -> x16f only (x16r never materialized; hgR(0) gathers inline)
    {
        GArgs a = { emb16, w16 + OFF_ER, nullptr, x16f, nullptr, b_er, x_source,
                    nullptr, Hsz, 0, 0, 0, Hsz, Esz, 0 };
        mega_kernel<<<OUT_NB, GT, GSM>>>(a, a, 0, OUT_NB, OUT_NX, OUT_NX, nullptr, nullptr);
    }

    // software-pipelined dual chains (round-11 schedule)
    {
        GArgs a = HG(0, 0);
        mega_kernel<<<HG_NB, GT, GSM>>>(a, a, 0, HG_NB, HG_NX, HG_NX, nullptr, nullptr);
    }
    for (int l = 0; l < Lsz; l++) {
        // hgR(l) ∥ scanF(l)
        {
            GArgs a = HG(l, 1);
            mega_kernel<<<NSCAN + HG_NB, GT, GSM>>>(a, a, NSCAN, HG_NB, HG_NX, HG_NX,
                                                    hg16f, h16f);
        }
        // outF(l) ∥ scanR(l)
        {
            GArgs a = (l == Lsz - 1) ? OUTf(0) : OUTm(l, 0);
            mega_kernel<<<NSCAN + OUT_NB, GT, GSM>>>(a, a, NSCAN, OUT_NB, OUT_NX, OUT_NX,
                                                     hg16r, h16r);
        }
        if (l + 1 < Lsz) {
            // hgF(l+1) ∥ outR(l)
            GArgs a0 = HG(l + 1, 0);
            GArgs a1 = OUTm(l, 1);
            mega_kernel<<<HG_NB + OUT_NB, GT, GSM>>>(a0, a1, 0, HG_NB, HG_NX, OUT_NX,
                                                     nullptr, nullptr);
        } else {
            // outR(last) -> fp32 out (rev row-mapped, cols [H,2H))
            GArgs a = OUTf(1);
            mega_kernel<<<OUT_NB, GT, GSM>>>(a, a, 0, OUT_NB, OUT_NX, OUT_NX,
                                             nullptr, nullptr);
        }
    }

    long long need = (long long)Msz * 2 * Hsz + (long long)Bsz * 2 * Hsz;
    if ((long long)out_size >= need)
        seq_kernel<<<Bsz, 256>>>(out, x_lengths, out + (size_t)Msz * 2 * Hsz);
}